// round 14
// baseline (speedup 1.0000x reference)
#include <cuda_runtime.h>
#include <stdint.h>
#include <math.h>

#define TSEQ 128
#define NPED 256
#define RNN  128
#define EMB  64
#define GG   16
#define OUTD 5
#define NCTA 128
#define TPB  512
#define CAP2 256
#define ASTR 260
#define BST  68
#define GSTR 68
#define HTS  20

// ---- persistent device scratch (no allocations allowed) ----
__device__ float d_h[2][NPED*RNN];            // double-buffered hidden state
__device__ float d_te_all[TSEQ*NPED*EMB];     // per-step social accumulators (pre-bias)
__device__ float d_ie[TSEQ*NPED*EMB];         // precomputed input embeddings
__device__ int   d_pairs2[TSEQ*GG*CAP2];      // pair lists bucketed by (t, rowgroup(j)): (i<<8)|(jl<<4)|cell
__device__ int   d_pcnt2[TSEQ*GG];
__device__ int   d_cnt_l[8];                  // sense barrier: per-group arrival counts
__device__ int   d_cnt_r;                     // sense barrier: root count
__device__ volatile int d_sense;              // sense barrier (2 flips/launch -> returns to 0)
__device__ __align__(64) int d_flagH[16][16]; // per-team h flags: d_flagH[rowt][rt] = t+1 (64B/team)
__device__ __align__(64) int d_cntT[16];      // sharded te barrier: 8 arrivals/shard/step

// full sense-reversal barrier (cold path: preamble + epilogue only)
__device__ __forceinline__ void gbar(int* lsense, int grp) {
    __syncthreads();
    if (threadIdx.x == 0) {
        int s = 1 - *lsense;
        *lsense = s;
        __threadfence();
        if (atomicAdd(&d_cnt_l[grp], 1) == 15) {
            d_cnt_l[grp] = 0;
            __threadfence();
            if (atomicAdd(&d_cnt_r, 1) == 7) {
                d_cnt_r = 0;
                __threadfence();
                d_sense = s;
            }
        }
        while (d_sense != s) { }
        __threadfence();
    }
    __syncthreads();
}

// te: release-red arrive (sharded)
__device__ __forceinline__ void arrive_rel(int* cnt) {
    __syncthreads();
    if (threadIdx.x == 0)
        asm volatile("red.release.gpu.global.add.s32 [%0], 1;" :: "l"(cnt) : "memory");
}
// te wait: sum 16 shards with 4 pipelined v4 relaxed loads, then acquire fence
__device__ __forceinline__ void waitT_shards(const int* cnt, int target) {
    if (threadIdx.x == 0) {
        int s;
        do {
            int4 v0, v1, v2, v3;
            asm volatile("ld.relaxed.gpu.global.v4.s32 {%0,%1,%2,%3}, [%4];"
                         : "=r"(v0.x),"=r"(v0.y),"=r"(v0.z),"=r"(v0.w) : "l"(cnt)      : "memory");
            asm volatile("ld.relaxed.gpu.global.v4.s32 {%0,%1,%2,%3}, [%4];"
                         : "=r"(v1.x),"=r"(v1.y),"=r"(v1.z),"=r"(v1.w) : "l"(cnt + 4)  : "memory");
            asm volatile("ld.relaxed.gpu.global.v4.s32 {%0,%1,%2,%3}, [%4];"
                         : "=r"(v2.x),"=r"(v2.y),"=r"(v2.z),"=r"(v2.w) : "l"(cnt + 8)  : "memory");
            asm volatile("ld.relaxed.gpu.global.v4.s32 {%0,%1,%2,%3}, [%4];"
                         : "=r"(v3.x),"=r"(v3.y),"=r"(v3.z),"=r"(v3.w) : "l"(cnt + 12) : "memory");
            s = v0.x+v0.y+v0.z+v0.w + v1.x+v1.y+v1.z+v1.w
              + v2.x+v2.y+v2.z+v2.w + v3.x+v3.y+v3.z+v3.w;
        } while (s < target);
        asm volatile("fence.acq_rel.gpu;" ::: "memory");
    }
    __syncthreads();
}
// h wait: poll 8 per-producer flags (independent loads), then acquire fence
__device__ __forceinline__ void waitH_flags(const int* fl, int t) {
    if (threadIdx.x == 0) {
        int mn;
        do {
            mn = 0x7fffffff;
            #pragma unroll
            for (int p = 0; p < 8; p++) {
                int v;
                asm volatile("ld.relaxed.gpu.global.s32 %0, [%1];" : "=r"(v) : "l"(fl + p) : "memory");
                mn = min(mn, v);
            }
        } while (mn < t);
        asm volatile("fence.acq_rel.gpu;" ::: "memory");
    }
    __syncthreads();
}

__device__ __forceinline__ float sigf(float x) {
    return __fdividef(1.f, 1.f + __expf(-x));
}
__device__ __forceinline__ float tanhfast(float x) {
    x = fminf(fmaxf(x, -15.f), 15.f);
    float e = __expf(2.f * x);
    return __fdividef(e - 1.f, e + 1.f);
}

// FFMA2 GEMM segment: u-chunks [U0,U1), A M-major (broadcast loads), B k-major
template<int U0, int U1>
__device__ __forceinline__ void gemm2(unsigned long long (&acc)[4][2],
                                      const float* Ab, const float* Bb) {
    #pragma unroll
    for (int u = U0; u < U1; u++) {
        float4 av[4];
        #pragma unroll
        for (int i = 0; i < 4; i++) av[i] = *(const float4*)(Ab + i*ASTR + u*32);
        #pragma unroll
        for (int kk = 0; kk < 4; kk++) {
            ulonglong2 b2 = *(const ulonglong2*)(Bb + (u*32 + kk)*BST);
            #pragma unroll
            for (int i = 0; i < 4; i++) {
                float a = (kk==0) ? av[i].x : (kk==1) ? av[i].y : (kk==2) ? av[i].z : av[i].w;
                unsigned long long a2;
                asm("mov.b64 %0, {%1, %1};" : "=l"(a2) : "f"(a));
                asm("fma.rn.f32x2 %0, %1, %2, %0;" : "+l"(acc[i][0]) : "l"(a2), "l"(b2.x));
                asm("fma.rn.f32x2 %0, %1, %2, %0;" : "+l"(acc[i][1]) : "l"(a2), "l"(b2.y));
            }
        }
    }
}

__global__ void __launch_bounds__(TPB, 1)
social_kernel(const float* __restrict__ V,
              const float* __restrict__ W_emb, const float* __restrict__ b_emb,
              const float* __restrict__ W_tens, const float* __restrict__ b_tens,
              const float* __restrict__ W_ih,  const float* __restrict__ b_ih,
              const float* __restrict__ W_hh,  const float* __restrict__ b_hh,
              const float* __restrict__ W_out, const float* __restrict__ b_out,
              float* __restrict__ out)
{
    extern __shared__ float sm[];
    float* B_s   = sm;                      // 256 x BST : persistent k-major [W_ih|W_hh] slice
    float* Wt_s  = B_s  + 256*BST;          // 16*16*64  : W_tens[cell][rl][e] for this CTA's r-slice
    float* A_s   = Wt_s + GG*16*64;         // 16 x ASTR : [ie 0..63 | te 64..127 | h 128..255]
    float* G_s   = A_s  + 16*ASTR;          // 16 x GSTR : gates tile
    float* h_tile= G_s  + 16*GSTR;          // 16 x HTS  : local h tile
    float* bt_s  = h_tile + 16*HTS;         // 64        : b_tens
    float* Wout_s= bt_s + 64;               // 80        : W_out[o][r0:r0+16]
    __shared__ int pl_s[CAP2];
    __shared__ int scnt2[GG];
    __shared__ int lsense;

    const int tid = threadIdx.x;
    const int b   = blockIdx.x;
    const int grp = b >> 4;

    if (tid == 0) lsense = 0;

    const int rowt = b >> 3, rt = b & 7;
    const int n0 = rowt*16, r0 = rt*16;
    const int nl = (tid >> 4) & 15, rl = tid & 15;   // valid for tid<256
    const int n  = n0 + nl,  r  = r0 + rl;

    // ---- zero h0; zero this CTA's slice of d_te_all; init out with bias ----
    if (tid < 256) d_h[0][b*256 + tid] = 0.f;
    {
        float* tz = d_te_all + b*(TSEQ*NPED*EMB/NCTA);
        for (int k = tid; k < TSEQ*NPED*EMB/NCTA; k += TPB) tz[k] = 0.f;
        float* oz = out + b*1280;   // TSEQ*NPED*OUTD = 128*1280
        for (int k = tid; k < 1280; k += TPB) oz[k] = b_out[k % OUTD];
    }

    // ---- precompute for frame t=b: positions, pair buckets by rowgroup(j), ie ----
    {
        const int t = b;
        float* xs = A_s;            // scratch reuse
        float* ys = A_s + NPED;
        if (tid < NPED) {
            xs[tid] = V[t*NPED + tid];
            ys[tid] = V[TSEQ*NPED + t*NPED + tid];
        }
        if (tid < GG) scnt2[tid] = 0;
        __syncthreads();
        if (tid < NPED) {
            const float WB  = (float)(64.0/720.0), WBH = (float)(32.0/720.0);
            const float HBv = (float)(64.0/576.0), HBH = (float)(32.0/576.0);
            const float xi = xs[tid], yi = ys[tid];
            const int i = tid;
            for (int j = 0; j < NPED; j++) {
                if (j == i) continue;
                float dx = xs[j] - xi;
                float dy = ys[j] - yi;
                int cx = (int)floorf((dx + WBH)/WB*4.0f);
                int cy = (int)floorf((dy + HBH)/HBv*4.0f);
                if (cx >= 0 && cx < 4 && cy >= 0 && cy < 4) {
                    int cell = cx + cy*4;
                    int rj = j >> 4;
                    int pos = atomicAdd(&scnt2[rj], 1);
                    if (pos < CAP2)
                        d_pairs2[(t*GG + rj)*CAP2 + pos] = (i << 8) | ((j & 15) << 4) | cell;
                }
            }
            float* iep = d_ie + (t*NPED + i)*EMB;
            #pragma unroll 8
            for (int e = 0; e < EMB; e++) {
                float v = fmaf(W_emb[2*e], xi, fmaf(W_emb[2*e+1], yi, b_emb[e]));
                iep[e] = fmaxf(v, 0.f);
            }
        }
        __syncthreads();
        if (tid < GG) d_pcnt2[t*GG + tid] = min(scnt2[tid], CAP2);
    }

    // ---- persistent smem weights: B k-major ----
    for (int idx = tid; idx < 64*256; idx += TPB) {
        int ql = idx >> 8, k = idx & 255;
        int q = (ql >> 4)*RNN + r0 + (ql & 15);
        B_s[k*BST + ql] = (k < RNN) ? W_ih[q*RNN + k] : W_hh[q*RNN + (k - RNN)];
    }
    for (int idx = tid; idx < GG*16*64; idx += TPB) {
        int e = idx & 63, rr = (idx >> 6) & 15, cell = idx >> 10;
        Wt_s[idx] = W_tens[e*(GG*RNN) + cell*RNN + r0 + rr];   // layout [cell][rl][e]
    }
    if (tid < EMB) bt_s[tid] = b_tens[tid];
    if (tid < OUTD*16) Wout_s[tid] = W_out[(tid >> 4)*RNN + r0 + (tid & 15)];

    // ---- per-thread recurrent registers (tid<256 own one (n,r)) ----
    float bi = 0.f, bf = 0.f, bg = 0.f, bo = 0.f;
    if (tid < 256) {
        bi = b_ih[r]         + b_hh[r];
        bf = b_ih[RNN+r]     + b_hh[RNN+r];
        bg = b_ih[2*RNN+r]   + b_hh[2*RNN+r];
        bo = b_ih[3*RNN+r]   + b_hh[3*RNN+r];
    }
    float creg = 0.f;
    float hv = 0.f;

    gbar(&lsense, grp);   // full barrier: preamble done

    // lane map: ks in lane bits 2..4 (in-warp shfl), row4 constant per warp (A broadcast)
    const int ks   = (tid >> 2) & 7;        // split-K=8
    const int warp = tid >> 5;              // 16 warps
    const int row4 = warp >> 2;             // 4 row groups (const per warp)
    const int q4   = (warp & 3)*4 + (tid & 3);  // 16 col groups

    const float* Ab_base = A_s + (row4*4)*ASTR + ks*4;
    const float* Bb_base = B_s + (ks*4)*BST + q4*4;

    for (int t = 0; t < TSEQ; t++) {
        const int pt = t & 1, pn = pt ^ 1;

        // ---- (0) parallel h-independent work: warps 8-15 prefetch pairs, warps 0-7 stage ie ----
        int cnt = 0;
        if (t < TSEQ-1) {
            cnt = d_pcnt2[(t+1)*GG + rowt];
            if (tid >= 256) {
                const int p = tid - 256;
                if (p < cnt) pl_s[p] = d_pairs2[((t+1)*GG + rowt)*CAP2 + p];
            }
        }
        if (tid < 256) {
            const float* iet = d_ie + t*NPED*EMB;
            const int m = tid >> 4, c4 = (tid & 15) << 2;
            *(float4*)(A_s + m*ASTR + c4) = *(const float4*)(iet + (n0 + m)*EMB + c4);
        }
        __syncthreads();

        // ---- (1) GEMM ie segment (k 0..63) -- before h wait ----
        unsigned long long acc[4][2];
        #pragma unroll
        for (int i = 0; i < 4; i++) { acc[i][0] = 0ULL; acc[i][1] = 0ULL; }
        gemm2<0,2>(acc, Ab_base, Bb_base);

        // ---- (2) wait for team h_t (8 per-producer flags) ----
        if (t > 0) waitH_flags(&d_flagH[rowt][0], t);

        // ---- (3) stage h columns: one LDG.128+STS.128 per thread ----
        {
            const float* hp = d_h[pt];
            const int m = tid >> 5, c4 = (tid & 31) << 2;
            *(float4*)(A_s + m*ASTR + 128 + c4) = *(const float4*)(hp + (n0 + m)*RNN + c4);
        }
        __syncthreads();

        // ---- (4) GEMM h segment (k 128..255) ----
        gemm2<4,8>(acc, Ab_base, Bb_base);

        // ---- (5) wait for te_t (16 shards; arrivals happened last step -> full slack) ----
        if (t > 0) waitT_shards(d_cntT, 128*t);

        // ---- (6) stage te columns: one LDG.128 + bias + relu + STS.128 per thread ----
        if (tid < 256) {
            const float* tep = d_te_all + t*NPED*EMB;
            const int m = tid >> 4, c4 = (tid & 15) << 2;
            float4 v = *(const float4*)(tep + (n0 + m)*EMB + c4);
            float4 bb = *(const float4*)(bt_s + c4);
            v.x = fmaxf(v.x + bb.x, 0.f);
            v.y = fmaxf(v.y + bb.y, 0.f);
            v.z = fmaxf(v.z + bb.z, 0.f);
            v.w = fmaxf(v.w + bb.w, 0.f);
            *(float4*)(A_s + m*ASTR + 64 + c4) = v;
        }
        __syncthreads();

        // ---- (7) GEMM te segment (k 64..127) ----
        gemm2<2,4>(acc, Ab_base, Bb_base);

        // ---- reduce over 8 k-slices (ks at lane bits 2..4 -> masks 4,8,16) ----
        {
            float red[16];
            #pragma unroll
            for (int i = 0; i < 4; i++)
                #pragma unroll
                for (int jp = 0; jp < 2; jp++) {
                    unsigned long long v = acc[i][jp];
                    red[i*4 + jp*2 + 0] = __int_as_float((int)(v & 0xffffffffULL));
                    red[i*4 + jp*2 + 1] = __int_as_float((int)(v >> 32));
                }
            #pragma unroll
            for (int x = 0; x < 16; x++) {
                float v = red[x];
                v += __shfl_xor_sync(0xffffffffu, v, 4);
                v += __shfl_xor_sync(0xffffffffu, v, 8);
                v += __shfl_xor_sync(0xffffffffu, v, 16);
                red[x] = v;
            }
            if (ks == 0) {
                #pragma unroll
                for (int i = 0; i < 4; i++)
                    #pragma unroll
                    for (int jj = 0; jj < 4; jj++)
                        G_s[(row4*4+i)*GSTR + q4*4 + jj] = red[i*4 + jj];
            }
        }
        __syncthreads();

        // ---- (8) LSTM pointwise (tid<256, each owns one (n,r)) ----
        if (tid < 256) {
            const float* gs = G_s + nl*GSTR + rl;
            float gi = gs[0]  + bi;
            float gf = gs[16] + bf;
            float gg = gs[32] + bg;
            float go = gs[48] + bo;
            float si = sigf(gi);
            float sf = sigf(gf);
            float so = sigf(go);
            creg = sf*creg + si*tanhfast(gg);
            hv = so*tanhfast(creg);
            h_tile[nl*HTS + rl] = hv;
            d_h[pn][n*RNN + r] = hv;
        }

        // ---- (9) publish h_{t+1}: release flag (plain store, no RMW) ----
        __syncthreads();
        if (tid == 0)
            asm volatile("st.release.gpu.global.b32 [%0], %1;"
                         :: "l"(&d_flagH[rowt][rt]), "r"(t + 1) : "memory");

        // ---- (10) social for te_{t+1}: local h_tile, off critical path ----
        if (t < TSEQ-1) {
            float* tew = d_te_all + (t+1)*NPED*EMB;
            const int pg = tid >> 6;    // 8 pair-groups of 64 threads
            const int e  = tid & 63;
            for (int p = pg; p < cnt; p += 8) {
                const int pr = pl_s[p];
                const int i  = pr >> 8, jl = (pr >> 4) & 15, cell = pr & 15;
                const float* wt = Wt_s + cell*(16*64) + e;
                const float4* h4 = (const float4*)(h_tile + jl*HTS);
                float s = 0.f;
                #pragma unroll
                for (int q = 0; q < 4; q++) {
                    float4 hq = h4[q];
                    const float* wq = wt + q*4*64;
                    s = fmaf(wq[0],   hq.x, s);
                    s = fmaf(wq[64],  hq.y, s);
                    s = fmaf(wq[128], hq.z, s);
                    s = fmaf(wq[192], hq.w, s);
                }
                atomicAdd(tew + i*EMB + e, s);
            }
            // ---- (11) announce te_{t+1} (sharded by rowt: 8 arrivals/shard) ----
            arrive_rel(d_cntT + rowt);
        }

        // ---- (12) output projection for step t (off critical path) ----
        if (tid < 256) {
            #pragma unroll
            for (int o = 0; o < OUTD; o++) {
                float pv = hv * Wout_s[o*16 + rl];
                pv += __shfl_xor_sync(0xffffffffu, pv, 8);
                pv += __shfl_xor_sync(0xffffffffu, pv, 4);
                pv += __shfl_xor_sync(0xffffffffu, pv, 2);
                pv += __shfl_xor_sync(0xffffffffu, pv, 1);
                if (rl == 0) atomicAdd(out + (t*NPED + n)*OUTD + o, pv);
            }
        }
    }

    gbar(&lsense, grp);  // full barrier; sense flips total = 2 (returns to 0)

    // reset monotonic counters/flags for the next graph replay
    if (b == 0) {
        if (tid < 16) d_cntT[tid] = 0;
        if (tid < 256) ((int*)d_flagH)[tid] = 0;
    }

    // ---- epilogue: hT, cT straight from registers ----
    if (tid < 256) {
        float* hT = out + TSEQ*NPED*OUTD;
        float* cT = hT + NPED*RNN;
        hT[n*RNN + r] = hv;
        cT[n*RNN + r] = creg;
    }
}

extern "C" void kernel_launch(void* const* d_in, const int* in_sizes, int n_in,
                              void* d_out, int out_size) {
    const float* V      = (const float*)d_in[0];
    // d_in[1] = PedsList (identity arange) -- unused by construction
    const float* W_emb  = (const float*)d_in[2];
    const float* b_emb  = (const float*)d_in[3];
    const float* W_tens = (const float*)d_in[4];
    const float* b_tens = (const float*)d_in[5];
    const float* W_ih   = (const float*)d_in[6];
    const float* b_ih   = (const float*)d_in[7];
    const float* W_hh   = (const float*)d_in[8];
    const float* b_hh   = (const float*)d_in[9];
    const float* W_out  = (const float*)d_in[10];
    const float* b_out  = (const float*)d_in[11];
    float* out = (float*)d_out;

    const int smem_bytes = (256*BST + GG*16*64 + 16*ASTR + 16*GSTR + 16*HTS + 64 + 80)
                           * (int)sizeof(float); // ~160 KB
    cudaFuncSetAttribute(social_kernel, cudaFuncAttributeMaxDynamicSharedMemorySize, smem_bytes);
    social_kernel<<<NCTA, TPB, smem_bytes>>>(V, W_emb, b_emb, W_tens, b_tens,
                                             W_ih, b_ih, W_hh, b_hh, W_out, b_out, out);
}

// round 15
// speedup vs baseline: 1.0127x; 1.0127x over previous
#include <cuda_runtime.h>
#include <stdint.h>
#include <math.h>

#define TSEQ 128
#define NPED 256
#define RNN  128
#define EMB  64
#define GG   16
#define OUTD 5
#define NCTA 128
#define TPB  512
#define CAP2 256
#define ASTR 260
#define BST  68
#define GSTR 68
#define HTS  20

// ---- persistent device scratch (no allocations allowed) ----
__device__ float d_h[2][NPED*RNN];            // double-buffered hidden state
__device__ float d_te_all[TSEQ*NPED*EMB];     // per-step social accumulators (pre-bias)
__device__ float d_ie[TSEQ*NPED*EMB];         // precomputed input embeddings
__device__ int   d_pairs2[TSEQ*GG*CAP2];      // pair lists bucketed by (t, rowgroup(j)): (i<<8)|(jl<<4)|cell
__device__ int   d_pcnt2[TSEQ*GG];
__device__ int   d_cnt_l[8];                  // sense barrier: per-group arrival counts
__device__ int   d_cnt_r;                     // sense barrier: root count
__device__ volatile int d_sense;              // sense barrier (2 flips/launch -> returns to 0)
__device__ int   d_cntH[16];                  // per-rowt-team monotonic barrier: h ready (8 arrivals/step)
__device__ int   d_cntT;                      // global monotonic barrier: te ready (128 arrivals/step)

// full sense-reversal barrier (cold path: preamble + epilogue only)
__device__ __forceinline__ void gbar(int* lsense, int grp) {
    __syncthreads();
    if (threadIdx.x == 0) {
        int s = 1 - *lsense;
        *lsense = s;
        __threadfence();
        if (atomicAdd(&d_cnt_l[grp], 1) == 15) {
            d_cnt_l[grp] = 0;
            __threadfence();
            if (atomicAdd(&d_cnt_r, 1) == 7) {
                d_cnt_r = 0;
                __threadfence();
                d_sense = s;
            }
        }
        while (d_sense != s) { }
        __threadfence();
    }
    __syncthreads();
}

// split-phase monotonic barrier: release-red arrive / relaxed-load spin + final acquire fence
__device__ __forceinline__ void arrive_rel(int* cnt) {
    __syncthreads();                    // CTA-wide happens-before into leader's release (CG grid-sync pattern)
    if (threadIdx.x == 0)
        asm volatile("red.release.gpu.global.add.s32 [%0], 1;" :: "l"(cnt) : "memory");
}
__device__ __forceinline__ void wait_cnt(const int* cnt, int target) {
    if (threadIdx.x == 0) {
        int v;
        do {
            asm volatile("ld.relaxed.gpu.global.s32 %0, [%1];" : "=r"(v) : "l"(cnt) : "memory");
        } while (v < target);
        asm volatile("fence.acq_rel.gpu;" ::: "memory");
    }
    __syncthreads();
}

__device__ __forceinline__ float sigf(float x) {
    return __fdividef(1.f, 1.f + __expf(-x));
}
__device__ __forceinline__ float tanhfast(float x) {
    x = fminf(fmaxf(x, -15.f), 15.f);
    float e = __expf(2.f * x);
    return __fdividef(e - 1.f, e + 1.f);
}

// FFMA2 GEMM segment: u-chunks [U0,U1), A M-major (broadcast loads), B k-major
template<int U0, int U1>
__device__ __forceinline__ void gemm2(unsigned long long (&acc)[4][2],
                                      const float* Ab, const float* Bb) {
    #pragma unroll
    for (int u = U0; u < U1; u++) {
        float4 av[4];
        #pragma unroll
        for (int i = 0; i < 4; i++) av[i] = *(const float4*)(Ab + i*ASTR + u*32);
        #pragma unroll
        for (int kk = 0; kk < 4; kk++) {
            ulonglong2 b2 = *(const ulonglong2*)(Bb + (u*32 + kk)*BST);
            #pragma unroll
            for (int i = 0; i < 4; i++) {
                float a = (kk==0) ? av[i].x : (kk==1) ? av[i].y : (kk==2) ? av[i].z : av[i].w;
                unsigned long long a2;
                asm("mov.b64 %0, {%1, %1};" : "=l"(a2) : "f"(a));
                asm("fma.rn.f32x2 %0, %1, %2, %0;" : "+l"(acc[i][0]) : "l"(a2), "l"(b2.x));
                asm("fma.rn.f32x2 %0, %1, %2, %0;" : "+l"(acc[i][1]) : "l"(a2), "l"(b2.y));
            }
        }
    }
}

__global__ void __launch_bounds__(TPB, 1)
social_kernel(const float* __restrict__ V,
              const float* __restrict__ W_emb, const float* __restrict__ b_emb,
              const float* __restrict__ W_tens, const float* __restrict__ b_tens,
              const float* __restrict__ W_ih,  const float* __restrict__ b_ih,
              const float* __restrict__ W_hh,  const float* __restrict__ b_hh,
              const float* __restrict__ W_out, const float* __restrict__ b_out,
              float* __restrict__ out)
{
    extern __shared__ float sm[];
    float* B_s   = sm;                      // 256 x BST : persistent k-major [W_ih|W_hh] slice
    float* Wt_s  = B_s  + 256*BST;          // 16*16*64  : W_tens[cell][rl][e] for this CTA's r-slice
    float* A_s   = Wt_s + GG*16*64;         // 16 x ASTR : [ie 0..63 | te 64..127 | h 128..255]
    float* G_s   = A_s  + 16*ASTR;          // 16 x GSTR : gates tile
    float* h_tile= G_s  + 16*GSTR;          // 16 x HTS  : local h tile
    float* bt_s  = h_tile + 16*HTS;         // 64        : b_tens
    float* Wout_s= bt_s + 64;               // 80        : W_out[o][r0:r0+16]
    __shared__ int pl_s[CAP2];
    __shared__ int scnt2[GG];
    __shared__ int lsense;

    const int tid = threadIdx.x;
    const int b   = blockIdx.x;
    const int grp = b >> 4;

    if (tid == 0) lsense = 0;

    const int rowt = b >> 3, rt = b & 7;
    const int n0 = rowt*16, r0 = rt*16;
    const int nl = (tid >> 4) & 15, rl = tid & 15;   // valid for tid<256
    const int n  = n0 + nl,  r  = r0 + rl;

    // ---- zero h0; zero this CTA's slice of d_te_all; init out with bias ----
    if (tid < 256) d_h[0][b*256 + tid] = 0.f;
    {
        float* tz = d_te_all + b*(TSEQ*NPED*EMB/NCTA);
        for (int k = tid; k < TSEQ*NPED*EMB/NCTA; k += TPB) tz[k] = 0.f;
        float* oz = out + b*1280;   // TSEQ*NPED*OUTD = 128*1280
        for (int k = tid; k < 1280; k += TPB) oz[k] = b_out[k % OUTD];
    }

    // ---- precompute for frame t=b: positions, pair buckets by rowgroup(j), ie ----
    {
        const int t = b;
        float* xs = A_s;            // scratch reuse
        float* ys = A_s + NPED;
        if (tid < NPED) {
            xs[tid] = V[t*NPED + tid];
            ys[tid] = V[TSEQ*NPED + t*NPED + tid];
        }
        if (tid < GG) scnt2[tid] = 0;
        __syncthreads();
        if (tid < NPED) {
            const float WB  = (float)(64.0/720.0), WBH = (float)(32.0/720.0);
            const float HBv = (float)(64.0/576.0), HBH = (float)(32.0/576.0);
            const float xi = xs[tid], yi = ys[tid];
            const int i = tid;
            for (int j = 0; j < NPED; j++) {
                if (j == i) continue;
                float dx = xs[j] - xi;
                float dy = ys[j] - yi;
                int cx = (int)floorf((dx + WBH)/WB*4.0f);
                int cy = (int)floorf((dy + HBH)/HBv*4.0f);
                if (cx >= 0 && cx < 4 && cy >= 0 && cy < 4) {
                    int cell = cx + cy*4;
                    int rj = j >> 4;
                    int pos = atomicAdd(&scnt2[rj], 1);
                    if (pos < CAP2)
                        d_pairs2[(t*GG + rj)*CAP2 + pos] = (i << 8) | ((j & 15) << 4) | cell;
                }
            }
            float* iep = d_ie + (t*NPED + i)*EMB;
            #pragma unroll 8
            for (int e = 0; e < EMB; e++) {
                float v = fmaf(W_emb[2*e], xi, fmaf(W_emb[2*e+1], yi, b_emb[e]));
                iep[e] = fmaxf(v, 0.f);
            }
        }
        __syncthreads();
        if (tid < GG) d_pcnt2[t*GG + tid] = min(scnt2[tid], CAP2);
    }

    // ---- persistent smem weights: B k-major ----
    for (int idx = tid; idx < 64*256; idx += TPB) {
        int ql = idx >> 8, k = idx & 255;
        int q = (ql >> 4)*RNN + r0 + (ql & 15);
        B_s[k*BST + ql] = (k < RNN) ? W_ih[q*RNN + k] : W_hh[q*RNN + (k - RNN)];
    }
    for (int idx = tid; idx < GG*16*64; idx += TPB) {
        int e = idx & 63, rr = (idx >> 6) & 15, cell = idx >> 10;
        Wt_s[idx] = W_tens[e*(GG*RNN) + cell*RNN + r0 + rr];   // layout [cell][rl][e]
    }
    if (tid < EMB) bt_s[tid] = b_tens[tid];
    if (tid < OUTD*16) Wout_s[tid] = W_out[(tid >> 4)*RNN + r0 + (tid & 15)];

    // ---- per-thread recurrent registers (tid<256 own one (n,r)) ----
    float bi = 0.f, bf = 0.f, bg = 0.f, bo = 0.f;
    if (tid < 256) {
        bi = b_ih[r]         + b_hh[r];
        bf = b_ih[RNN+r]     + b_hh[RNN+r];
        bg = b_ih[2*RNN+r]   + b_hh[2*RNN+r];
        bo = b_ih[3*RNN+r]   + b_hh[3*RNN+r];
    }
    float creg = 0.f;
    float hv = 0.f;

    gbar(&lsense, grp);   // full barrier: preamble done

    // lane map: ks in lane bits 2..4 (in-warp shfl), row4 constant per warp (A broadcast)
    const int ks   = (tid >> 2) & 7;        // split-K=8
    const int warp = tid >> 5;              // 16 warps
    const int row4 = warp >> 2;             // 4 row groups (const per warp)
    const int q4   = (warp & 3)*4 + (tid & 3);  // 16 col groups

    const float* Ab_base = A_s + (row4*4)*ASTR + ks*4;
    const float* Bb_base = B_s + (ks*4)*BST + q4*4;

    for (int t = 0; t < TSEQ; t++) {
        const int pt = t & 1, pn = pt ^ 1;

        // ---- (0) parallel h-independent work: warps 8-15 prefetch pairs, warps 0-7 stage ie ----
        int cnt = 0;
        if (t < TSEQ-1) {
            cnt = d_pcnt2[(t+1)*GG + rowt];
            if (tid >= 256) {
                const int p = tid - 256;
                if (p < cnt) pl_s[p] = d_pairs2[((t+1)*GG + rowt)*CAP2 + p];
            }
        }
        if (tid < 256) {
            const float* iet = d_ie + t*NPED*EMB;
            const int m = tid >> 4, c4 = (tid & 15) << 2;
            *(float4*)(A_s + m*ASTR + c4) = *(const float4*)(iet + (n0 + m)*EMB + c4);
        }
        __syncthreads();

        // ---- (1) GEMM ie segment (k 0..63) -- before h wait ----
        unsigned long long acc[4][2];
        #pragma unroll
        for (int i = 0; i < 4; i++) { acc[i][0] = 0ULL; acc[i][1] = 0ULL; }
        gemm2<0,2>(acc, Ab_base, Bb_base);

        // ---- (2) wait for team h_t (single counter, single-load poll) ----
        if (t > 0) wait_cnt(d_cntH + rowt, 8*t);

        // ---- (3) stage h columns: one LDG.128+STS.128 per thread (512 threads) ----
        {
            const float* hp = d_h[pt];
            const int m = tid >> 5, c4 = (tid & 31) << 2;
            *(float4*)(A_s + m*ASTR + 128 + c4) = *(const float4*)(hp + (n0 + m)*RNN + c4);
        }
        __syncthreads();

        // ---- (4) GEMM h segment (k 128..255) ----
        gemm2<4,8>(acc, Ab_base, Bb_base);

        // ---- (5) wait for te_t (single counter; arrivals happened last step -> full slack) ----
        if (t > 0) wait_cnt(&d_cntT, 128*t);

        // ---- (6) stage te columns: one LDG.128 + bias + relu + STS.128 per thread ----
        if (tid < 256) {
            const float* tep = d_te_all + t*NPED*EMB;
            const int m = tid >> 4, c4 = (tid & 15) << 2;
            float4 v = *(const float4*)(tep + (n0 + m)*EMB + c4);
            float4 bb = *(const float4*)(bt_s + c4);
            v.x = fmaxf(v.x + bb.x, 0.f);
            v.y = fmaxf(v.y + bb.y, 0.f);
            v.z = fmaxf(v.z + bb.z, 0.f);
            v.w = fmaxf(v.w + bb.w, 0.f);
            *(float4*)(A_s + m*ASTR + 64 + c4) = v;
        }
        __syncthreads();

        // ---- (7) GEMM te segment (k 64..127) ----
        gemm2<2,4>(acc, Ab_base, Bb_base);

        // ---- reduce over 8 k-slices (ks at lane bits 2..4 -> masks 4,8,16) ----
        {
            float red[16];
            #pragma unroll
            for (int i = 0; i < 4; i++)
                #pragma unroll
                for (int jp = 0; jp < 2; jp++) {
                    unsigned long long v = acc[i][jp];
                    red[i*4 + jp*2 + 0] = __int_as_float((int)(v & 0xffffffffULL));
                    red[i*4 + jp*2 + 1] = __int_as_float((int)(v >> 32));
                }
            #pragma unroll
            for (int x = 0; x < 16; x++) {
                float v = red[x];
                v += __shfl_xor_sync(0xffffffffu, v, 4);
                v += __shfl_xor_sync(0xffffffffu, v, 8);
                v += __shfl_xor_sync(0xffffffffu, v, 16);
                red[x] = v;
            }
            if (ks == 0) {
                #pragma unroll
                for (int i = 0; i < 4; i++)
                    #pragma unroll
                    for (int jj = 0; jj < 4; jj++)
                        G_s[(row4*4+i)*GSTR + q4*4 + jj] = red[i*4 + jj];
            }
        }
        __syncthreads();

        // ---- (8) LSTM pointwise (tid<256, each owns one (n,r)) ----
        if (tid < 256) {
            const float* gs = G_s + nl*GSTR + rl;
            float gi = gs[0]  + bi;
            float gf = gs[16] + bf;
            float gg = gs[32] + bg;
            float go = gs[48] + bo;
            float si = sigf(gi);
            float sf = sigf(gf);
            float so = sigf(go);
            creg = sf*creg + si*tanhfast(gg);
            hv = so*tanhfast(creg);
            h_tile[nl*HTS + rl] = hv;
            d_h[pn][n*RNN + r] = hv;
        }

        // ---- (9) announce h_{t+1} to team ----
        arrive_rel(d_cntH + rowt);

        // ---- (10) social for te_{t+1}: local h_tile, off critical path ----
        if (t < TSEQ-1) {
            float* tew = d_te_all + (t+1)*NPED*EMB;
            const int pg = tid >> 6;    // 8 pair-groups of 64 threads
            const int e  = tid & 63;
            for (int p = pg; p < cnt; p += 8) {
                const int pr = pl_s[p];
                const int i  = pr >> 8, jl = (pr >> 4) & 15, cell = pr & 15;
                const float* wt = Wt_s + cell*(16*64) + e;
                const float4* h4 = (const float4*)(h_tile + jl*HTS);
                float s = 0.f;
                #pragma unroll
                for (int q = 0; q < 4; q++) {
                    float4 hq = h4[q];
                    const float* wq = wt + q*4*64;
                    s = fmaf(wq[0],   hq.x, s);
                    s = fmaf(wq[64],  hq.y, s);
                    s = fmaf(wq[128], hq.z, s);
                    s = fmaf(wq[192], hq.w, s);
                }
                atomicAdd(tew + i*EMB + e, s);
            }
            // ---- (11) announce te_{t+1} (single global counter) ----
            arrive_rel(&d_cntT);
        }

        // ---- (12) output projection for step t (off critical path) ----
        if (tid < 256) {
            #pragma unroll
            for (int o = 0; o < OUTD; o++) {
                float pv = hv * Wout_s[o*16 + rl];
                pv += __shfl_xor_sync(0xffffffffu, pv, 8);
                pv += __shfl_xor_sync(0xffffffffu, pv, 4);
                pv += __shfl_xor_sync(0xffffffffu, pv, 2);
                pv += __shfl_xor_sync(0xffffffffu, pv, 1);
                if (rl == 0) atomicAdd(out + (t*NPED + n)*OUTD + o, pv);
            }
        }
    }

    gbar(&lsense, grp);  // full barrier; sense flips total = 2 (returns to 0)

    // reset monotonic counters for the next graph replay
    if (b == 0) {
        if (tid < 16) d_cntH[tid] = 0;
        if (tid == 16) d_cntT = 0;
    }

    // ---- epilogue: hT, cT straight from registers ----
    if (tid < 256) {
        float* hT = out + TSEQ*NPED*OUTD;
        float* cT = hT + NPED*RNN;
        hT[n*RNN + r] = hv;
        cT[n*RNN + r] = creg;
    }
}

extern "C" void kernel_launch(void* const* d_in, const int* in_sizes, int n_in,
                              void* d_out, int out_size) {
    const float* V      = (const float*)d_in[0];
    // d_in[1] = PedsList (identity arange) -- unused by construction
    const float* W_emb  = (const float*)d_in[2];
    const float* b_emb  = (const float*)d_in[3];
    const float* W_tens = (const float*)d_in[4];
    const float* b_tens = (const float*)d_in[5];
    const float* W_ih   = (const float*)d_in[6];
    const float* b_ih   = (const float*)d_in[7];
    const float* W_hh   = (const float*)d_in[8];
    const float* b_hh   = (const float*)d_in[9];
    const float* W_out  = (const float*)d_in[10];
    const float* b_out  = (const float*)d_in[11];
    float* out = (float*)d_out;

    const int smem_bytes = (256*BST + GG*16*64 + 16*ASTR + 16*GSTR + 16*HTS + 64 + 80)
                           * (int)sizeof(float); // ~160 KB
    cudaFuncSetAttribute(social_kernel, cudaFuncAttributeMaxDynamicSharedMemorySize, smem_bytes);
    social_kernel<<<NCTA, TPB, smem_bytes>>>(V, W_emb, b_emb, W_tens, b_tens,
                                             W_ih, b_ih, W_hh, b_hh, W_out, b_out, out);
}

// round 16
// speedup vs baseline: 1.0741x; 1.0607x over previous
#include <cuda_runtime.h>
#include <stdint.h>
#include <math.h>

#define TSEQ 128
#define NPED 256
#define RNN  128
#define EMB  64
#define GG   16
#define OUTD 5
#define NCTA 128
#define TPB  512
#define CAP2 256
#define ASTR 260
#define BST  68
#define GSTR 68
#define HTS  20

// ---- persistent device scratch (no allocations allowed) ----
__device__ float d_h[2][NPED*RNN];            // double-buffered hidden state
__device__ float d_te_all[TSEQ*NPED*EMB];     // per-step social accumulators (pre-bias)
__device__ float d_ie[TSEQ*NPED*EMB];         // precomputed input embeddings
__device__ int   d_pairs2[TSEQ*GG*CAP2];      // pair lists bucketed by (t, rowgroup(j)): (i<<8)|(jl<<4)|cell
__device__ int   d_pcnt2[TSEQ*GG];
__device__ int   d_cnt_l[8];                  // sense barrier: per-group arrival counts
__device__ int   d_cnt_r;                     // sense barrier: root count
__device__ volatile int d_sense;              // sense barrier (2 flips/launch -> returns to 0)
__device__ int   d_cntH[16];                  // per-rowt-team monotonic barrier: h ready (8 arrivals/step)
__device__ int   d_cntT;                      // global monotonic barrier: te ready (128 arrivals/step)

// full sense-reversal barrier (cold path: preamble + epilogue only)
__device__ __forceinline__ void gbar(int* lsense, int grp) {
    __syncthreads();
    if (threadIdx.x == 0) {
        int s = 1 - *lsense;
        *lsense = s;
        __threadfence();
        if (atomicAdd(&d_cnt_l[grp], 1) == 15) {
            d_cnt_l[grp] = 0;
            __threadfence();
            if (atomicAdd(&d_cnt_r, 1) == 7) {
                d_cnt_r = 0;
                __threadfence();
                d_sense = s;
            }
        }
        while (d_sense != s) { }
        __threadfence();
    }
    __syncthreads();
}

// split-phase monotonic barrier: release-red arrive / acquire-load spin (R12 recipe — no standalone fences)
__device__ __forceinline__ void arrive_rel(int* cnt) {
    __syncthreads();
    if (threadIdx.x == 0)
        asm volatile("red.release.gpu.global.add.s32 [%0], 1;" :: "l"(cnt) : "memory");
}
__device__ __forceinline__ void wait_cnt(const int* cnt, int target) {
    if (threadIdx.x == 0) {
        int v;
        do {
            asm volatile("ld.acquire.gpu.global.s32 %0, [%1];" : "=r"(v) : "l"(cnt) : "memory");
        } while (v < target);
    }
    __syncthreads();
}

__device__ __forceinline__ float sigf(float x) {
    return __fdividef(1.f, 1.f + __expf(-x));
}
__device__ __forceinline__ float tanhfast(float x) {
    x = fminf(fmaxf(x, -15.f), 15.f);
    float e = __expf(2.f * x);
    return __fdividef(e - 1.f, e + 1.f);
}

// FFMA2 GEMM segment: u-chunks [U0,U1), A M-major (broadcast loads), B k-major
template<int U0, int U1>
__device__ __forceinline__ void gemm2(unsigned long long (&acc)[4][2],
                                      const float* Ab, const float* Bb) {
    #pragma unroll
    for (int u = U0; u < U1; u++) {
        float4 av[4];
        #pragma unroll
        for (int i = 0; i < 4; i++) av[i] = *(const float4*)(Ab + i*ASTR + u*32);
        #pragma unroll
        for (int kk = 0; kk < 4; kk++) {
            ulonglong2 b2 = *(const ulonglong2*)(Bb + (u*32 + kk)*BST);
            #pragma unroll
            for (int i = 0; i < 4; i++) {
                float a = (kk==0) ? av[i].x : (kk==1) ? av[i].y : (kk==2) ? av[i].z : av[i].w;
                unsigned long long a2;
                asm("mov.b64 %0, {%1, %1};" : "=l"(a2) : "f"(a));
                asm("fma.rn.f32x2 %0, %1, %2, %0;" : "+l"(acc[i][0]) : "l"(a2), "l"(b2.x));
                asm("fma.rn.f32x2 %0, %1, %2, %0;" : "+l"(acc[i][1]) : "l"(a2), "l"(b2.y));
            }
        }
    }
}

__global__ void __launch_bounds__(TPB, 1)
social_kernel(const float* __restrict__ V,
              const float* __restrict__ W_emb, const float* __restrict__ b_emb,
              const float* __restrict__ W_tens, const float* __restrict__ b_tens,
              const float* __restrict__ W_ih,  const float* __restrict__ b_ih,
              const float* __restrict__ W_hh,  const float* __restrict__ b_hh,
              const float* __restrict__ W_out, const float* __restrict__ b_out,
              float* __restrict__ out)
{
    extern __shared__ float sm[];
    float* B_s   = sm;                      // 256 x BST : persistent k-major [W_ih|W_hh] slice
    float* Wt_s  = B_s  + 256*BST;          // 16*16*64  : W_tens[cell][rl][e] for this CTA's r-slice
    float* A_s   = Wt_s + GG*16*64;         // 16 x ASTR : [ie 0..63 | te 64..127 | h 128..255]
    float* G_s   = A_s  + 16*ASTR;          // 16 x GSTR : gates tile
    float* h_tile= G_s  + 16*GSTR;          // 16 x HTS  : local h tile
    float* bt_s  = h_tile + 16*HTS;         // 64        : b_tens
    float* Wout_s= bt_s + 64;               // 80        : W_out[o][r0:r0+16]
    __shared__ int pl_s[CAP2];
    __shared__ int scnt2[GG];
    __shared__ int lsense;

    const int tid = threadIdx.x;
    const int b   = blockIdx.x;
    const int grp = b >> 4;

    if (tid == 0) lsense = 0;

    const int rowt = b >> 3, rt = b & 7;
    const int n0 = rowt*16, r0 = rt*16;
    const int nl = (tid >> 4) & 15, rl = tid & 15;   // valid for tid<256
    const int n  = n0 + nl,  r  = r0 + rl;

    // ---- zero h0; zero this CTA's slice of d_te_all; init out with bias ----
    if (tid < 256) d_h[0][b*256 + tid] = 0.f;
    {
        float* tz = d_te_all + b*(TSEQ*NPED*EMB/NCTA);
        for (int k = tid; k < TSEQ*NPED*EMB/NCTA; k += TPB) tz[k] = 0.f;
        float* oz = out + b*1280;   // TSEQ*NPED*OUTD = 128*1280
        for (int k = tid; k < 1280; k += TPB) oz[k] = b_out[k % OUTD];
    }

    // ---- precompute for frame t=b: positions, pair buckets by rowgroup(j), ie ----
    {
        const int t = b;
        float* xs = A_s;            // scratch reuse
        float* ys = A_s + NPED;
        if (tid < NPED) {
            xs[tid] = V[t*NPED + tid];
            ys[tid] = V[TSEQ*NPED + t*NPED + tid];
        }
        if (tid < GG) scnt2[tid] = 0;
        __syncthreads();
        if (tid < NPED) {
            const float WB  = (float)(64.0/720.0), WBH = (float)(32.0/720.0);
            const float HBv = (float)(64.0/576.0), HBH = (float)(32.0/576.0);
            const float xi = xs[tid], yi = ys[tid];
            const int i = tid;
            for (int j = 0; j < NPED; j++) {
                if (j == i) continue;
                float dx = xs[j] - xi;
                float dy = ys[j] - yi;
                int cx = (int)floorf((dx + WBH)/WB*4.0f);
                int cy = (int)floorf((dy + HBH)/HBv*4.0f);
                if (cx >= 0 && cx < 4 && cy >= 0 && cy < 4) {
                    int cell = cx + cy*4;
                    int rj = j >> 4;
                    int pos = atomicAdd(&scnt2[rj], 1);
                    if (pos < CAP2)
                        d_pairs2[(t*GG + rj)*CAP2 + pos] = (i << 8) | ((j & 15) << 4) | cell;
                }
            }
            float* iep = d_ie + (t*NPED + i)*EMB;
            #pragma unroll 8
            for (int e = 0; e < EMB; e++) {
                float v = fmaf(W_emb[2*e], xi, fmaf(W_emb[2*e+1], yi, b_emb[e]));
                iep[e] = fmaxf(v, 0.f);
            }
        }
        __syncthreads();
        if (tid < GG) d_pcnt2[t*GG + tid] = min(scnt2[tid], CAP2);
    }

    // ---- persistent smem weights: B k-major ----
    for (int idx = tid; idx < 64*256; idx += TPB) {
        int ql = idx >> 8, k = idx & 255;
        int q = (ql >> 4)*RNN + r0 + (ql & 15);
        B_s[k*BST + ql] = (k < RNN) ? W_ih[q*RNN + k] : W_hh[q*RNN + (k - RNN)];
    }
    for (int idx = tid; idx < GG*16*64; idx += TPB) {
        int e = idx & 63, rr = (idx >> 6) & 15, cell = idx >> 10;
        Wt_s[idx] = W_tens[e*(GG*RNN) + cell*RNN + r0 + rr];   // layout [cell][rl][e]
    }
    if (tid < EMB) bt_s[tid] = b_tens[tid];
    if (tid < OUTD*16) Wout_s[tid] = W_out[(tid >> 4)*RNN + r0 + (tid & 15)];

    // ---- per-thread recurrent registers (tid<256 own one (n,r)) ----
    float bi = 0.f, bf = 0.f, bg = 0.f, bo = 0.f;
    if (tid < 256) {
        bi = b_ih[r]         + b_hh[r];
        bf = b_ih[RNN+r]     + b_hh[RNN+r];
        bg = b_ih[2*RNN+r]   + b_hh[2*RNN+r];
        bo = b_ih[3*RNN+r]   + b_hh[3*RNN+r];
    }
    float creg = 0.f;
    float hv = 0.f;

    gbar(&lsense, grp);   // full barrier: preamble done

    // lane map: ks in lane bits 2..4 (in-warp shfl), row4 constant per warp (A broadcast)
    const int ks   = (tid >> 2) & 7;        // split-K=8
    const int warp = tid >> 5;              // 16 warps
    const int row4 = warp >> 2;             // 4 row groups (const per warp)
    const int q4   = (warp & 3)*4 + (tid & 3);  // 16 col groups

    const float* Ab_base = A_s + (row4*4)*ASTR + ks*4;
    const float* Bb_base = B_s + (ks*4)*BST + q4*4;

    for (int t = 0; t < TSEQ; t++) {
        const int pt = t & 1, pn = pt ^ 1;

        // ---- (0) h-independent: pair list t+1 (any thread), stage ie (float4, tid<256) ----
        int cnt = 0;
        if (t < TSEQ-1) {
            cnt = d_pcnt2[(t+1)*GG + rowt];
            if (tid < cnt) pl_s[tid] = d_pairs2[((t+1)*GG + rowt)*CAP2 + tid];
        }
        if (tid < 256) {
            const float* iet = d_ie + t*NPED*EMB;
            const int m = tid >> 4, c4 = (tid & 15) << 2;
            *(float4*)(A_s + m*ASTR + c4) = *(const float4*)(iet + (n0 + m)*EMB + c4);
        }
        __syncthreads();

        // ---- (1) GEMM ie segment (k 0..63) -- before h wait ----
        unsigned long long acc[4][2];
        #pragma unroll
        for (int i = 0; i < 4; i++) { acc[i][0] = 0ULL; acc[i][1] = 0ULL; }
        gemm2<0,2>(acc, Ab_base, Bb_base);

        // ---- (2) wait for team h_t (single counter, acquire-load poll) ----
        if (t > 0) wait_cnt(d_cntH + rowt, 8*t);

        // ---- (3) stage h columns: one LDG.128+STS.128 per thread (512 threads) ----
        {
            const float* hp = d_h[pt];
            const int m = tid >> 5, c4 = (tid & 31) << 2;
            *(float4*)(A_s + m*ASTR + 128 + c4) = *(const float4*)(hp + (n0 + m)*RNN + c4);
        }
        __syncthreads();

        // ---- (4) GEMM h segment (k 128..255) ----
        gemm2<4,8>(acc, Ab_base, Bb_base);

        // ---- (5) wait for te_t (single counter; arrivals happened last step -> full slack) ----
        if (t > 0) wait_cnt(&d_cntT, 128*t);

        // ---- (6) stage te columns: one LDG.128 + bias + relu + STS.128 per thread ----
        if (tid < 256) {
            const float* tep = d_te_all + t*NPED*EMB;
            const int m = tid >> 4, c4 = (tid & 15) << 2;
            float4 v = *(const float4*)(tep + (n0 + m)*EMB + c4);
            float4 bb = *(const float4*)(bt_s + c4);
            v.x = fmaxf(v.x + bb.x, 0.f);
            v.y = fmaxf(v.y + bb.y, 0.f);
            v.z = fmaxf(v.z + bb.z, 0.f);
            v.w = fmaxf(v.w + bb.w, 0.f);
            *(float4*)(A_s + m*ASTR + 64 + c4) = v;
        }
        __syncthreads();

        // ---- (7) GEMM te segment (k 64..127) ----
        gemm2<2,4>(acc, Ab_base, Bb_base);

        // ---- reduce over 8 k-slices (ks at lane bits 2..4 -> masks 4,8,16) ----
        {
            float red[16];
            #pragma unroll
            for (int i = 0; i < 4; i++)
                #pragma unroll
                for (int jp = 0; jp < 2; jp++) {
                    unsigned long long v = acc[i][jp];
                    red[i*4 + jp*2 + 0] = __int_as_float((int)(v & 0xffffffffULL));
                    red[i*4 + jp*2 + 1] = __int_as_float((int)(v >> 32));
                }
            #pragma unroll
            for (int x = 0; x < 16; x++) {
                float v = red[x];
                v += __shfl_xor_sync(0xffffffffu, v, 4);
                v += __shfl_xor_sync(0xffffffffu, v, 8);
                v += __shfl_xor_sync(0xffffffffu, v, 16);
                red[x] = v;
            }
            if (ks == 0) {
                #pragma unroll
                for (int i = 0; i < 4; i++)
                    #pragma unroll
                    for (int jj = 0; jj < 4; jj++)
                        G_s[(row4*4+i)*GSTR + q4*4 + jj] = red[i*4 + jj];
            }
        }
        __syncthreads();

        // ---- (8) LSTM pointwise (tid<256, each owns one (n,r)) ----
        if (tid < 256) {
            const float* gs = G_s + nl*GSTR + rl;
            float gi = gs[0]  + bi;
            float gf = gs[16] + bf;
            float gg = gs[32] + bg;
            float go = gs[48] + bo;
            float si = sigf(gi);
            float sf = sigf(gf);
            float so = sigf(go);
            creg = sf*creg + si*tanhfast(gg);
            hv = so*tanhfast(creg);
            h_tile[nl*HTS + rl] = hv;
            d_h[pn][n*RNN + r] = hv;
        }

        // ---- (9) announce h_{t+1} to team ----
        arrive_rel(d_cntH + rowt);

        // ---- (10) social for te_{t+1}: local h_tile, off critical path ----
        if (t < TSEQ-1) {
            float* tew = d_te_all + (t+1)*NPED*EMB;
            const int pg = tid >> 6;    // 8 pair-groups of 64 threads
            const int e  = tid & 63;
            for (int p = pg; p < cnt; p += 8) {
                const int pr = pl_s[p];
                const int i  = pr >> 8, jl = (pr >> 4) & 15, cell = pr & 15;
                const float* wt = Wt_s + cell*(16*64) + e;
                const float4* h4 = (const float4*)(h_tile + jl*HTS);
                float s = 0.f;
                #pragma unroll
                for (int q = 0; q < 4; q++) {
                    float4 hq = h4[q];
                    const float* wq = wt + q*4*64;
                    s = fmaf(wq[0],   hq.x, s);
                    s = fmaf(wq[64],  hq.y, s);
                    s = fmaf(wq[128], hq.z, s);
                    s = fmaf(wq[192], hq.w, s);
                }
                atomicAdd(tew + i*EMB + e, s);
            }
            // ---- (11) announce te_{t+1} (single global counter) ----
            arrive_rel(&d_cntT);
        }

        // ---- (12) output projection for step t (off critical path) ----
        if (tid < 256) {
            #pragma unroll
            for (int o = 0; o < OUTD; o++) {
                float pv = hv * Wout_s[o*16 + rl];
                pv += __shfl_xor_sync(0xffffffffu, pv, 8);
                pv += __shfl_xor_sync(0xffffffffu, pv, 4);
                pv += __shfl_xor_sync(0xffffffffu, pv, 2);
                pv += __shfl_xor_sync(0xffffffffu, pv, 1);
                if (rl == 0) atomicAdd(out + (t*NPED + n)*OUTD + o, pv);
            }
        }
    }

    gbar(&lsense, grp);  // full barrier; sense flips total = 2 (returns to 0)

    // reset monotonic counters for the next graph replay
    if (b == 0) {
        if (tid < 16) d_cntH[tid] = 0;
        if (tid == 16) d_cntT = 0;
    }

    // ---- epilogue: hT, cT straight from registers ----
    if (tid < 256) {
        float* hT = out + TSEQ*NPED*OUTD;
        float* cT = hT + NPED*RNN;
        hT[n*RNN + r] = hv;
        cT[n*RNN + r] = creg;
    }
}

extern "C" void kernel_launch(void* const* d_in, const int* in_sizes, int n_in,
                              void* d_out, int out_size) {
    const float* V      = (const float*)d_in[0];
    // d_in[1] = PedsList (identity arange) -- unused by construction
    const float* W_emb  = (const float*)d_in[2];
    const float* b_emb  = (const float*)d_in[3];
    const float* W_tens = (const float*)d_in[4];
    const float* b_tens = (const float*)d_in[5];
    const float* W_ih   = (const float*)d_in[6];
    const float* b_ih   = (const float*)d_in[7];
    const float* W_hh   = (const float*)d_in[8];
    const float* b_hh   = (const float*)d_in[9];
    const float* W_out  = (const float*)d_in[10];
    const float* b_out  = (const float*)d_in[11];
    float* out = (float*)d_out;

    const int smem_bytes = (256*BST + GG*16*64 + 16*ASTR + 16*GSTR + 16*HTS + 64 + 80)
                           * (int)sizeof(float); // ~160 KB
    cudaFuncSetAttribute(social_kernel, cudaFuncAttributeMaxDynamicSharedMemorySize, smem_bytes);
    social_kernel<<<NCTA, TPB, smem_bytes>>>(V, W_emb, b_emb, W_tens, b_tens,
                                             W_ih, b_ih, W_hh, b_hh, W_out, b_out, out);
}

// round 17
// speedup vs baseline: 1.1250x; 1.0474x over previous
#include <cuda_runtime.h>
#include <stdint.h>
#include <math.h>

#define TSEQ 128
#define NPED 256
#define RNN  128
#define EMB  64
#define GG   16
#define OUTD 5
#define NCTA 128
#define TPB  512
#define CAP2 256
#define ASTR 260
#define BST  68
#define GSTR 68
#define HTS  20

// ---- persistent device scratch (no allocations allowed) ----
__device__ float d_h[2][NPED*RNN];            // double-buffered hidden state
__device__ float d_te_all[TSEQ*NPED*EMB];     // per-step social accumulators (pre-bias)
__device__ float d_ie[TSEQ*NPED*EMB];         // precomputed input embeddings
__device__ int   d_pairs2[TSEQ*GG*CAP2];      // pair lists bucketed by (t, rowgroup(j)): (i<<8)|(jl<<4)|cell
__device__ int   d_pcnt2[TSEQ*GG];
__device__ int   d_cnt_l[8];                  // sense barrier: per-group arrival counts
__device__ int   d_cnt_r;                     // sense barrier: root count
__device__ volatile int d_sense;              // sense barrier (2 flips/launch -> returns to 0)
__device__ int   d_cntH[16];                  // per-rowt-team monotonic barrier: h ready (8 arrivals/step)
__device__ int   d_cntT;                      // global monotonic barrier: te ready (128 arrivals/step)

// full sense-reversal barrier (cold path: preamble + epilogue only)
__device__ __forceinline__ void gbar(int* lsense, int grp) {
    __syncthreads();
    if (threadIdx.x == 0) {
        int s = 1 - *lsense;
        *lsense = s;
        __threadfence();
        if (atomicAdd(&d_cnt_l[grp], 1) == 15) {
            d_cnt_l[grp] = 0;
            __threadfence();
            if (atomicAdd(&d_cnt_r, 1) == 7) {
                d_cnt_r = 0;
                __threadfence();
                d_sense = s;
            }
        }
        while (d_sense != s) { }
        __threadfence();
    }
    __syncthreads();
}

// split-phase monotonic barrier: release-red arrive / acquire-load spin.
// 8 pollers in 8 DIFFERENT warps drift out of phase -> sampling interval ~RTT/8.
__device__ __forceinline__ void arrive_rel(int* cnt) {
    __syncthreads();
    if (threadIdx.x == 0)
        asm volatile("red.release.gpu.global.add.s32 [%0], 1;" :: "l"(cnt) : "memory");
}
__device__ __forceinline__ void wait_cnt(const int* cnt, int target) {
    if ((threadIdx.x & 63) == 0) {       // lanes 0 of warps 0,2,4,...,14
        int v;
        do {
            asm volatile("ld.acquire.gpu.global.s32 %0, [%1];" : "=r"(v) : "l"(cnt) : "memory");
        } while (v < target);
    }
    __syncthreads();
}

__device__ __forceinline__ float sigf(float x) {
    return __fdividef(1.f, 1.f + __expf(-x));
}
__device__ __forceinline__ float tanhfast(float x) {
    x = fminf(fmaxf(x, -15.f), 15.f);
    float e = __expf(2.f * x);
    return __fdividef(e - 1.f, e + 1.f);
}

// FFMA2 GEMM segment: u-chunks [U0,U1), A M-major (broadcast loads), B k-major
template<int U0, int U1>
__device__ __forceinline__ void gemm2(unsigned long long (&acc)[4][2],
                                      const float* Ab, const float* Bb) {
    #pragma unroll
    for (int u = U0; u < U1; u++) {
        float4 av[4];
        #pragma unroll
        for (int i = 0; i < 4; i++) av[i] = *(const float4*)(Ab + i*ASTR + u*32);
        #pragma unroll
        for (int kk = 0; kk < 4; kk++) {
            ulonglong2 b2 = *(const ulonglong2*)(Bb + (u*32 + kk)*BST);
            #pragma unroll
            for (int i = 0; i < 4; i++) {
                float a = (kk==0) ? av[i].x : (kk==1) ? av[i].y : (kk==2) ? av[i].z : av[i].w;
                unsigned long long a2;
                asm("mov.b64 %0, {%1, %1};" : "=l"(a2) : "f"(a));
                asm("fma.rn.f32x2 %0, %1, %2, %0;" : "+l"(acc[i][0]) : "l"(a2), "l"(b2.x));
                asm("fma.rn.f32x2 %0, %1, %2, %0;" : "+l"(acc[i][1]) : "l"(a2), "l"(b2.y));
            }
        }
    }
}

__global__ void __launch_bounds__(TPB, 1)
social_kernel(const float* __restrict__ V,
              const float* __restrict__ W_emb, const float* __restrict__ b_emb,
              const float* __restrict__ W_tens, const float* __restrict__ b_tens,
              const float* __restrict__ W_ih,  const float* __restrict__ b_ih,
              const float* __restrict__ W_hh,  const float* __restrict__ b_hh,
              const float* __restrict__ W_out, const float* __restrict__ b_out,
              float* __restrict__ out)
{
    extern __shared__ float sm[];
    float* B_s   = sm;                      // 256 x BST : persistent k-major [W_ih|W_hh] slice
    float* Wt_s  = B_s  + 256*BST;          // 16*16*64  : W_tens[cell][rl][e] for this CTA's r-slice
    float* A_s   = Wt_s + GG*16*64;         // 16 x ASTR : [ie 0..63 | te 64..127 | h 128..255]
    float* G_s   = A_s  + 16*ASTR;          // 16 x GSTR : gates tile
    float* h_tile= G_s  + 16*GSTR;          // 16 x HTS  : local h tile
    float* bt_s  = h_tile + 16*HTS;         // 64        : b_tens
    float* Wout_s= bt_s + 64;               // 80        : W_out[o][r0:r0+16]
    __shared__ int pl_s[CAP2];
    __shared__ int scnt2[GG];
    __shared__ int lsense;

    const int tid = threadIdx.x;
    const int b   = blockIdx.x;
    const int grp = b >> 4;

    if (tid == 0) lsense = 0;

    const int rowt = b >> 3, rt = b & 7;
    const int n0 = rowt*16, r0 = rt*16;
    const int nl = (tid >> 4) & 15, rl = tid & 15;   // valid for tid<256
    const int n  = n0 + nl,  r  = r0 + rl;

    // ---- zero h0; zero this CTA's slice of d_te_all; init out with bias ----
    if (tid < 256) d_h[0][b*256 + tid] = 0.f;
    {
        float* tz = d_te_all + b*(TSEQ*NPED*EMB/NCTA);
        for (int k = tid; k < TSEQ*NPED*EMB/NCTA; k += TPB) tz[k] = 0.f;
        float* oz = out + b*1280;   // TSEQ*NPED*OUTD = 128*1280
        for (int k = tid; k < 1280; k += TPB) oz[k] = b_out[k % OUTD];
    }

    // ---- precompute for frame t=b: positions, pair buckets by rowgroup(j), ie ----
    {
        const int t = b;
        float* xs = A_s;            // scratch reuse
        float* ys = A_s + NPED;
        if (tid < NPED) {
            xs[tid] = V[t*NPED + tid];
            ys[tid] = V[TSEQ*NPED + t*NPED + tid];
        }
        if (tid < GG) scnt2[tid] = 0;
        __syncthreads();
        if (tid < NPED) {
            const float WB  = (float)(64.0/720.0), WBH = (float)(32.0/720.0);
            const float HBv = (float)(64.0/576.0), HBH = (float)(32.0/576.0);
            const float xi = xs[tid], yi = ys[tid];
            const int i = tid;
            for (int j = 0; j < NPED; j++) {
                if (j == i) continue;
                float dx = xs[j] - xi;
                float dy = ys[j] - yi;
                int cx = (int)floorf((dx + WBH)/WB*4.0f);
                int cy = (int)floorf((dy + HBH)/HBv*4.0f);
                if (cx >= 0 && cx < 4 && cy >= 0 && cy < 4) {
                    int cell = cx + cy*4;
                    int rj = j >> 4;
                    int pos = atomicAdd(&scnt2[rj], 1);
                    if (pos < CAP2)
                        d_pairs2[(t*GG + rj)*CAP2 + pos] = (i << 8) | ((j & 15) << 4) | cell;
                }
            }
            float* iep = d_ie + (t*NPED + i)*EMB;
            #pragma unroll 8
            for (int e = 0; e < EMB; e++) {
                float v = fmaf(W_emb[2*e], xi, fmaf(W_emb[2*e+1], yi, b_emb[e]));
                iep[e] = fmaxf(v, 0.f);
            }
        }
        __syncthreads();
        if (tid < GG) d_pcnt2[t*GG + tid] = min(scnt2[tid], CAP2);
    }

    // ---- persistent smem weights: B k-major ----
    for (int idx = tid; idx < 64*256; idx += TPB) {
        int ql = idx >> 8, k = idx & 255;
        int q = (ql >> 4)*RNN + r0 + (ql & 15);
        B_s[k*BST + ql] = (k < RNN) ? W_ih[q*RNN + k] : W_hh[q*RNN + (k - RNN)];
    }
    for (int idx = tid; idx < GG*16*64; idx += TPB) {
        int e = idx & 63, rr = (idx >> 6) & 15, cell = idx >> 10;
        Wt_s[idx] = W_tens[e*(GG*RNN) + cell*RNN + r0 + rr];   // layout [cell][rl][e]
    }
    if (tid < EMB) bt_s[tid] = b_tens[tid];
    if (tid < OUTD*16) Wout_s[tid] = W_out[(tid >> 4)*RNN + r0 + (tid & 15)];

    // ---- per-thread recurrent registers (tid<256 own one (n,r)) ----
    float bi = 0.f, bf = 0.f, bg = 0.f, bo = 0.f;
    if (tid < 256) {
        bi = b_ih[r]         + b_hh[r];
        bf = b_ih[RNN+r]     + b_hh[RNN+r];
        bg = b_ih[2*RNN+r]   + b_hh[2*RNN+r];
        bo = b_ih[3*RNN+r]   + b_hh[3*RNN+r];
    }
    float creg = 0.f;
    float hv = 0.f;

    gbar(&lsense, grp);   // full barrier: preamble done

    // lane map: ks in lane bits 2..4 (in-warp shfl), row4 constant per warp (A broadcast)
    const int ks   = (tid >> 2) & 7;        // split-K=8
    const int warp = tid >> 5;              // 16 warps
    const int row4 = warp >> 2;             // 4 row groups (const per warp)
    const int q4   = (warp & 3)*4 + (tid & 3);  // 16 col groups

    const float* Ab_base = A_s + (row4*4)*ASTR + ks*4;
    const float* Bb_base = B_s + (ks*4)*BST + q4*4;

    for (int t = 0; t < TSEQ; t++) {
        const int pt = t & 1, pn = pt ^ 1;

        // ---- (0) parallel h-independent work: warps 8-15 prefetch pairs, warps 0-7 stage ie ----
        int cnt = 0;
        if (t < TSEQ-1) {
            cnt = d_pcnt2[(t+1)*GG + rowt];
            if (tid >= 256) {
                const int p = tid - 256;
                if (p < cnt) pl_s[p] = d_pairs2[((t+1)*GG + rowt)*CAP2 + p];
            }
        }
        if (tid < 256) {
            const float* iet = d_ie + t*NPED*EMB;
            const int m = tid >> 4, c4 = (tid & 15) << 2;
            *(float4*)(A_s + m*ASTR + c4) = *(const float4*)(iet + (n0 + m)*EMB + c4);
        }
        __syncthreads();

        // ---- (1) GEMM ie segment (k 0..63) -- before h wait ----
        unsigned long long acc[4][2];
        #pragma unroll
        for (int i = 0; i < 4; i++) { acc[i][0] = 0ULL; acc[i][1] = 0ULL; }
        gemm2<0,2>(acc, Ab_base, Bb_base);

        // ---- (2) wait for team h_t (single counter, 8 staggered pollers) ----
        if (t > 0) wait_cnt(d_cntH + rowt, 8*t);

        // ---- (3) stage h columns: one LDG.128+STS.128 per thread (512 threads) ----
        {
            const float* hp = d_h[pt];
            const int m = tid >> 5, c4 = (tid & 31) << 2;
            *(float4*)(A_s + m*ASTR + 128 + c4) = *(const float4*)(hp + (n0 + m)*RNN + c4);
        }
        __syncthreads();

        // ---- (4) GEMM h segment (k 128..255) ----
        gemm2<4,8>(acc, Ab_base, Bb_base);

        // ---- (5) wait for te_t (single counter; arrivals happened last step -> full slack) ----
        if (t > 0) wait_cnt(&d_cntT, 128*t);

        // ---- (6) stage te columns: one LDG.128 + bias + relu + STS.128 per thread ----
        if (tid < 256) {
            const float* tep = d_te_all + t*NPED*EMB;
            const int m = tid >> 4, c4 = (tid & 15) << 2;
            float4 v = *(const float4*)(tep + (n0 + m)*EMB + c4);
            float4 bb = *(const float4*)(bt_s + c4);
            v.x = fmaxf(v.x + bb.x, 0.f);
            v.y = fmaxf(v.y + bb.y, 0.f);
            v.z = fmaxf(v.z + bb.z, 0.f);
            v.w = fmaxf(v.w + bb.w, 0.f);
            *(float4*)(A_s + m*ASTR + 64 + c4) = v;
        }
        __syncthreads();

        // ---- (7) GEMM te segment (k 64..127) ----
        gemm2<2,4>(acc, Ab_base, Bb_base);

        // ---- reduce over 8 k-slices (ks at lane bits 2..4 -> masks 4,8,16) ----
        {
            float red[16];
            #pragma unroll
            for (int i = 0; i < 4; i++)
                #pragma unroll
                for (int jp = 0; jp < 2; jp++) {
                    unsigned long long v = acc[i][jp];
                    red[i*4 + jp*2 + 0] = __int_as_float((int)(v & 0xffffffffULL));
                    red[i*4 + jp*2 + 1] = __int_as_float((int)(v >> 32));
                }
            #pragma unroll
            for (int x = 0; x < 16; x++) {
                float v = red[x];
                v += __shfl_xor_sync(0xffffffffu, v, 4);
                v += __shfl_xor_sync(0xffffffffu, v, 8);
                v += __shfl_xor_sync(0xffffffffu, v, 16);
                red[x] = v;
            }
            if (ks == 0) {
                #pragma unroll
                for (int i = 0; i < 4; i++)
                    #pragma unroll
                    for (int jj = 0; jj < 4; jj++)
                        G_s[(row4*4+i)*GSTR + q4*4 + jj] = red[i*4 + jj];
            }
        }
        __syncthreads();

        // ---- (8) LSTM pointwise (tid<256, each owns one (n,r)) ----
        if (tid < 256) {
            const float* gs = G_s + nl*GSTR + rl;
            float gi = gs[0]  + bi;
            float gf = gs[16] + bf;
            float gg = gs[32] + bg;
            float go = gs[48] + bo;
            float si = sigf(gi);
            float sf = sigf(gf);
            float so = sigf(go);
            creg = sf*creg + si*tanhfast(gg);
            hv = so*tanhfast(creg);
            h_tile[nl*HTS + rl] = hv;
            d_h[pn][n*RNN + r] = hv;
        }

        // ---- (9) announce h_{t+1} to team ----
        arrive_rel(d_cntH + rowt);

        // ---- (10) social for te_{t+1}: local h_tile, off critical path ----
        if (t < TSEQ-1) {
            float* tew = d_te_all + (t+1)*NPED*EMB;
            const int pg = tid >> 6;    // 8 pair-groups of 64 threads
            const int e  = tid & 63;
            for (int p = pg; p < cnt; p += 8) {
                const int pr = pl_s[p];
                const int i  = pr >> 8, jl = (pr >> 4) & 15, cell = pr & 15;
                const float* wt = Wt_s + cell*(16*64) + e;
                const float4* h4 = (const float4*)(h_tile + jl*HTS);
                float s = 0.f;
                #pragma unroll
                for (int q = 0; q < 4; q++) {
                    float4 hq = h4[q];
                    const float* wq = wt + q*4*64;
                    s = fmaf(wq[0],   hq.x, s);
                    s = fmaf(wq[64],  hq.y, s);
                    s = fmaf(wq[128], hq.z, s);
                    s = fmaf(wq[192], hq.w, s);
                }
                atomicAdd(tew + i*EMB + e, s);
            }
            // ---- (11) announce te_{t+1} (single global counter) ----
            arrive_rel(&d_cntT);
        }

        // ---- (12) output projection for step t (off critical path) ----
        if (tid < 256) {
            #pragma unroll
            for (int o = 0; o < OUTD; o++) {
                float pv = hv * Wout_s[o*16 + rl];
                pv += __shfl_xor_sync(0xffffffffu, pv, 8);
                pv += __shfl_xor_sync(0xffffffffu, pv, 4);
                pv += __shfl_xor_sync(0xffffffffu, pv, 2);
                pv += __shfl_xor_sync(0xffffffffu, pv, 1);
                if (rl == 0) atomicAdd(out + (t*NPED + n)*OUTD + o, pv);
            }
        }
    }

    gbar(&lsense, grp);  // full barrier; sense flips total = 2 (returns to 0)

    // reset monotonic counters for the next graph replay
    if (b == 0) {
        if (tid < 16) d_cntH[tid] = 0;
        if (tid == 16) d_cntT = 0;
    }

    // ---- epilogue: hT, cT straight from registers ----
    if (tid < 256) {
        float* hT = out + TSEQ*NPED*OUTD;
        float* cT = hT + NPED*RNN;
        hT[n*RNN + r] = hv;
        cT[n*RNN + r] = creg;
    }
}

extern "C" void kernel_launch(void* const* d_in, const int* in_sizes, int n_in,
                              void* d_out, int out_size) {
    const float* V      = (const float*)d_in[0];
    // d_in[1] = PedsList (identity arange) -- unused by construction
    const float* W_emb  = (const float*)d_in[2];
    const float* b_emb  = (const float*)d_in[3];
    const float* W_tens = (const float*)d_in[4];
    const float* b_tens = (const float*)d_in[5];
    const float* W_ih   = (const float*)d_in[6];
    const float* b_ih   = (const float*)d_in[7];
    const float* W_hh   = (const float*)d_in[8];
    const float* b_hh   = (const float*)d_in[9];
    const float* W_out  = (const float*)d_in[10];
    const float* b_out  = (const float*)d_in[11];
    float* out = (float*)d_out;

    const int smem_bytes = (256*BST + GG*16*64 + 16*ASTR + 16*GSTR + 16*HTS + 64 + 80)
                           * (int)sizeof(float); // ~160 KB
    cudaFuncSetAttribute(social_kernel, cudaFuncAttributeMaxDynamicSharedMemorySize, smem_bytes);
    social_kernel<<<NCTA, TPB, smem_bytes>>>(V, W_emb, b_emb, W_tens, b_tens,
                                             W_ih, b_ih, W_hh, b_hh, W_out, b_out, out);
}